// round 3
// baseline (speedup 1.0000x reference)
#include <cuda_runtime.h>

// ---------------- problem constants ----------------
#define CIN    2312
#define HID    300
#define NOUT   10
#define BATCH  128
#define T0     50
#define PAD    5
#define TP1    55          // T0 + PAD
#define T1     51          // conv1 output length
#define HP     56          // T1 + PAD
#define T2     52          // conv2 output length
#define KS     5
#define K1TOT  (KS*CIN)    // 11560
#define K2TOT  (KS*HID)    // 1500
#define M1     (BATCH*T1)  // 6528
#define M2     (BATCH*T2)  // 6656
#define BETA   0.9f
#define THRESH 1.0f

#define NIT    723                 // ceil(11560/16)
#define K1PAD  (NIT*16)            // 11568 (rows 11560..11567 of B1 stay zero)

// ---------------- scratch (device globals; zero-initialized, no allocation) ----------------
__device__ float g_Xpad[BATCH*TP1*CIN + 16];  // [B][55][CIN] + slack for padded-K over-read
__device__ float g_B1[(size_t)K1PAD*HID];     // [kk=(dt*CIN+i)][o]; pad rows never written => 0
__device__ float g_Y1[(size_t)M1*HID];        // [b*T1+t][HID]
__device__ float g_Hpad[BATCH*HP*HID];        // [B][56][HID]  spikes, left-padded
__device__ float g_B2t[NOUT*K2TOT];           // [o][kk=(dt*HID+h)]
__device__ float g_Y2[M2*NOUT];               // [b*T2+t][NOUT]

// ---------------- packed f32x2 helpers ----------------
__device__ __forceinline__ void fma2(unsigned long long& d,
                                     unsigned long long a,
                                     unsigned long long b) {
    asm("fma.rn.f32x2 %0, %1, %2, %3;" : "=l"(d) : "l"(a), "l"(b), "l"(d));
}
__device__ __forceinline__ void add2(unsigned long long& d, unsigned long long a) {
    asm("add.rn.f32x2 %0, %1, %2;" : "=l"(d) : "l"(d), "l"(a));
}

// ---------------- prep: pad + copy input ----------------
__global__ void prep_x(const float* __restrict__ data) {
    const int C4 = CIN / 4;                 // 578
    const int PER_B = TP1 * C4;             // 31790
    int v = blockIdx.x * blockDim.x + threadIdx.x;
    if (v >= BATCH * PER_B) return;
    int b = v / PER_B;
    int r = v - b * PER_B;
    int t = r / C4;
    int i4 = r - t * C4;
    float4 val = make_float4(0.f, 0.f, 0.f, 0.f);
    if (t >= PAD) {
        val = reinterpret_cast<const float4*>(data)[(b * T0 + (t - PAD)) * C4 + i4];
    }
    reinterpret_cast<float4*>(g_Xpad)[v] = val;
}

// ---------------- DCLS gaussian kernel synthesis ----------------
__device__ __forceinline__ void gauss5(float p, float g[KS]) {
    float c = p + 2.0f;
    float s = 0.f;
#pragma unroll
    for (int k = 0; k < KS; k++) {
        float d = ((float)k - c) * 0.5f;
        g[k] = expf(-0.5f * (d * d));
        s += g[k];
    }
    float den = s + 1e-7f;
#pragma unroll
    for (int k = 0; k < KS; k++) g[k] = g[k] / den;
}

__global__ void make_B1(const float* __restrict__ W1, const float* __restrict__ P1) {
    int tid = blockIdx.x * blockDim.x + threadIdx.x;
    if (tid >= CIN * HID) return;
    int i = tid / HID;
    int o = tid - i * HID;
    float w = W1[o * CIN + i];
    float p = P1[o * CIN + i];
    float g[KS];
    gauss5(p, g);
#pragma unroll
    for (int k = 0; k < KS; k++) {
        g_B1[(size_t)(k * CIN + i) * HID + o] = w * g[k];
    }
}

__global__ void make_B2(const float* __restrict__ W2, const float* __restrict__ P2) {
    int tid = blockIdx.x * blockDim.x + threadIdx.x;
    if (tid >= HID * NOUT) return;
    int h = tid / NOUT;
    int o = tid - h * NOUT;
    float w = W2[o * HID + h];
    float p = P2[o * HID + h];
    float g[KS];
    gauss5(p, g);
#pragma unroll
    for (int k = 0; k < KS; k++) {
        g_B2t[o * K2TOT + k * HID + h] = w * g[k];
    }
}

// ---------------- GEMM1, FFMA2 edition ----------------
// Y1[m, o] = sum_kk A[m, kk] * B1[kk, o] + b1[o]
// BM=128, BN=64, BK=16, 256 threads, 8x4 scalar micro-tile = 4 M-pairs x 4 cols f32x2.
// As[k][m] (k-major) -> a M-pairs free via LDS.128. Bsd holds each B value duplicated
// (v,v) -> b broadcast pairs free via LDS.128. Zero pack MOVs in the inner loop.
// Two-level accumulation: flush low->high every 16 iters (256 k terms) — identical
// order to round-2 kernel (bit-compatible).
__global__ void __launch_bounds__(256, 2) gemm1(const float* __restrict__ b1f) {
    __shared__ __align__(16) float As[2][16][128];
    __shared__ __align__(16) float Bsd[2][16][128];

    const int n0 = blockIdx.x * 64;
    const int m0 = blockIdx.y * 128;
    const int tid = threadIdx.x;

    // A loader: thread -> (row ar, col-offset ac4); 2 float4 per iter (BK=16)
    const int ar = tid >> 1;
    const int ac4 = (tid & 1) * 4;
    const int m = m0 + ar;
    const int bb = m / T1;
    const int tt = m - bb * T1;
    const float* Arow = g_Xpad + (size_t)(bb * TP1 + tt) * CIN;

    // B loader: thread -> (k-row bkr, col bnc); 1 float4 per iter, stored duplicated
    const int bkr = tid >> 4;                 // 0..15
    const int bnc = (tid & 15) * 4;           // 0..60
    const bool bload = (n0 + bnc + 3) < HID;
    const float* Bptr = g_B1 + (size_t)bkr * HID + n0 + bnc;
    const size_t bstep = (size_t)16 * HID;

    // compute mapping: rows tr*8..tr*8+7 (4 pairs), cols tc*4..tc*4+3
    const int tr = tid >> 4;
    const int tc = tid & 15;

    typedef unsigned long long u64;
    u64 accL[4][4], accH[4][4];
#pragma unroll
    for (int i = 0; i < 4; i++)
#pragma unroll
        for (int j = 0; j < 4; j++) { accL[i][j] = 0ull; accH[i][j] = 0ull; }

    // prologue: fill stage 0
    {
        float4 a0 = *reinterpret_cast<const float4*>(Arow + ac4);
        float4 a1 = *reinterpret_cast<const float4*>(Arow + 8 + ac4);
        float4 bv = make_float4(0.f, 0.f, 0.f, 0.f);
        if (bload) bv = *reinterpret_cast<const float4*>(Bptr);
        As[0][ac4 + 0][ar] = a0.x;  As[0][ac4 + 1][ar] = a0.y;
        As[0][ac4 + 2][ar] = a0.z;  As[0][ac4 + 3][ar] = a0.w;
        As[0][ac4 + 8][ar] = a1.x;  As[0][ac4 + 9][ar] = a1.y;
        As[0][ac4 +10][ar] = a1.z;  As[0][ac4 +11][ar] = a1.w;
        *reinterpret_cast<float4*>(&Bsd[0][bkr][bnc * 2])     = make_float4(bv.x, bv.x, bv.y, bv.y);
        *reinterpret_cast<float4*>(&Bsd[0][bkr][bnc * 2 + 4]) = make_float4(bv.z, bv.z, bv.w, bv.w);
    }
    __syncthreads();

    for (int it = 0; it < NIT; ++it) {
        const int cur = it & 1;
        const bool more = (it + 1) < NIT;
        float4 a0n, a1n, bvn;
        if (more) {
            const float* Ap = Arow + (it + 1) * 16;
            a0n = *reinterpret_cast<const float4*>(Ap + ac4);
            a1n = *reinterpret_cast<const float4*>(Ap + 8 + ac4);
            bvn = make_float4(0.f, 0.f, 0.f, 0.f);
            if (bload) bvn = *reinterpret_cast<const float4*>(Bptr + (size_t)(it + 1) * bstep);
        }

#pragma unroll
        for (int kk = 0; kk < 16; kk++) {
            ulonglong2 aq0 = *reinterpret_cast<const ulonglong2*>(&As[cur][kk][tr * 8]);
            ulonglong2 aq1 = *reinterpret_cast<const ulonglong2*>(&As[cur][kk][tr * 8 + 4]);
            ulonglong2 bq0 = *reinterpret_cast<const ulonglong2*>(&Bsd[cur][kk][tc * 8]);
            ulonglong2 bq1 = *reinterpret_cast<const ulonglong2*>(&Bsd[cur][kk][tc * 8 + 4]);
            fma2(accL[0][0], aq0.x, bq0.x);  fma2(accL[0][1], aq0.x, bq0.y);
            fma2(accL[0][2], aq0.x, bq1.x);  fma2(accL[0][3], aq0.x, bq1.y);
            fma2(accL[1][0], aq0.y, bq0.x);  fma2(accL[1][1], aq0.y, bq0.y);
            fma2(accL[1][2], aq0.y, bq1.x);  fma2(accL[1][3], aq0.y, bq1.y);
            fma2(accL[2][0], aq1.x, bq0.x);  fma2(accL[2][1], aq1.x, bq0.y);
            fma2(accL[2][2], aq1.x, bq1.x);  fma2(accL[2][3], aq1.x, bq1.y);
            fma2(accL[3][0], aq1.y, bq0.x);  fma2(accL[3][1], aq1.y, bq0.y);
            fma2(accL[3][2], aq1.y, bq1.x);  fma2(accL[3][3], aq1.y, bq1.y);
        }

        if ((it & 15) == 15) {     // flush every 256 k terms (same boundaries as round 2)
#pragma unroll
            for (int i = 0; i < 4; i++)
#pragma unroll
                for (int j = 0; j < 4; j++) { add2(accH[i][j], accL[i][j]); accL[i][j] = 0ull; }
        }

        if (more) {
            const int nxt = cur ^ 1;
            As[nxt][ac4 + 0][ar] = a0n.x;  As[nxt][ac4 + 1][ar] = a0n.y;
            As[nxt][ac4 + 2][ar] = a0n.z;  As[nxt][ac4 + 3][ar] = a0n.w;
            As[nxt][ac4 + 8][ar] = a1n.x;  As[nxt][ac4 + 9][ar] = a1n.y;
            As[nxt][ac4 +10][ar] = a1n.z;  As[nxt][ac4 +11][ar] = a1n.w;
            *reinterpret_cast<float4*>(&Bsd[nxt][bkr][bnc * 2])     = make_float4(bvn.x, bvn.x, bvn.y, bvn.y);
            *reinterpret_cast<float4*>(&Bsd[nxt][bkr][bnc * 2 + 4]) = make_float4(bvn.z, bvn.z, bvn.w, bvn.w);
            __syncthreads();
        }
    }
    // final flush (tail iters; adding exact zeros is a no-op numerically)
#pragma unroll
    for (int i = 0; i < 4; i++)
#pragma unroll
        for (int j = 0; j < 4; j++) add2(accH[i][j], accL[i][j]);

    // epilogue: unpack pairs, add bias, store
#pragma unroll
    for (int i = 0; i < 4; i++) {
        int row0 = m0 + tr * 8 + 2 * i;
#pragma unroll
        for (int j = 0; j < 4; j++) {
            int n = n0 + tc * 4 + j;
            if (n < HID) {
                float2 v = *reinterpret_cast<float2*>(&accH[i][j]);
                float bias = b1f[n];
                g_Y1[(size_t)row0 * HID + n]       = v.x + bias;
                g_Y1[(size_t)(row0 + 1) * HID + n] = v.y + bias;
            }
        }
    }
}

// ---------------- LIF layer 1 ----------------
__global__ void lif1() {
    int tid = blockIdx.x * blockDim.x + threadIdx.x;
    if (tid >= BATCH * HID) return;
    int b = tid / HID;
    int h = tid - b * HID;
#pragma unroll
    for (int tp = 0; tp < PAD; tp++)
        g_Hpad[(size_t)(b * HP + tp) * HID + h] = 0.f;
    float mem = 0.f;
    for (int t = 0; t < T1; t++) {
        float x = g_Y1[(size_t)(b * T1 + t) * HID + h];
        float reset = (mem > THRESH) ? 1.f : 0.f;
        mem = __fmaf_rn(BETA, mem, x) - reset * THRESH;
        float spk = (mem > THRESH) ? 1.f : 0.f;
        g_Hpad[(size_t)(b * HP + PAD + t) * HID + h] = spk;
    }
}

// ---------------- GEMM2: one warp per output row ----------------
__global__ void gemm2(const float* __restrict__ b2) {
    int gw = (blockIdx.x * blockDim.x + threadIdx.x) >> 5;
    int lane = threadIdx.x & 31;
    if (gw >= M2) return;
    int b = gw / T2;
    int t = gw - b * T2;
    const float* Arow = g_Hpad + (size_t)(b * HP + t) * HID;

    float acc[NOUT];
#pragma unroll
    for (int o = 0; o < NOUT; o++) acc[o] = 0.f;

    for (int kk = lane; kk < K2TOT; kk += 32) {
        float x = Arow[kk];
#pragma unroll
        for (int o = 0; o < NOUT; o++)
            acc[o] = __fmaf_rn(x, g_B2t[o * K2TOT + kk], acc[o]);
    }
#pragma unroll
    for (int o = 0; o < NOUT; o++) {
#pragma unroll
        for (int off = 16; off > 0; off >>= 1)
            acc[o] += __shfl_down_sync(0xffffffffu, acc[o], off);
    }
    if (lane == 0) {
#pragma unroll
        for (int o = 0; o < NOUT; o++)
            g_Y2[(size_t)gw * NOUT + o] = acc[o] + b2[o];
    }
}

// ---------------- LIF layer 2: spk2 and mem2 straight to d_out ----------------
__global__ void lif2(float* __restrict__ out) {
    int tid = blockIdx.x * blockDim.x + threadIdx.x;
    if (tid >= BATCH * NOUT) return;
    int b = tid / NOUT;
    int o = tid - b * NOUT;
    const int HALF = T2 * BATCH * NOUT;
    float mem = 0.f;
    for (int t = 0; t < T2; t++) {
        float x = g_Y2[(size_t)(b * T2 + t) * NOUT + o];
        float reset = (mem > THRESH) ? 1.f : 0.f;
        mem = __fmaf_rn(BETA, mem, x) - reset * THRESH;
        float spk = (mem > THRESH) ? 1.f : 0.f;
        int idx = (t * BATCH + b) * NOUT + o;
        out[idx] = spk;
        out[HALF + idx] = mem;
    }
}

// ---------------- launch ----------------
extern "C" void kernel_launch(void* const* d_in, const int* in_sizes, int n_in,
                              void* d_out, int out_size) {
    const float* data = (const float*)d_in[0];
    const float* W1   = (const float*)d_in[1];
    const float* P1   = (const float*)d_in[2];
    const float* b1   = (const float*)d_in[3];
    const float* W2   = (const float*)d_in[4];
    const float* P2   = (const float*)d_in[5];
    const float* b2   = (const float*)d_in[6];
    float* out = (float*)d_out;

    {
        int n4 = BATCH * TP1 * (CIN / 4);
        prep_x<<<(n4 + 255) / 256, 256>>>(data);
    }
    make_B1<<<(CIN * HID + 255) / 256, 256>>>(W1, P1);
    make_B2<<<(HID * NOUT + 255) / 256, 256>>>(W2, P2);

    {
        dim3 grid(5, 51);
        gemm1<<<grid, 256>>>(b1);
    }
    lif1<<<(BATCH * HID + 255) / 256, 256>>>();

    {
        int blocks = (M2 * 32 + 255) / 256;
        gemm2<<<blocks, 256>>>(b2);
    }
    lif2<<<(BATCH * NOUT + 255) / 256, 256>>>(out);
}

// round 4
// speedup vs baseline: 1.3945x; 1.3945x over previous
#include <cuda_runtime.h>

// ---------------- problem constants ----------------
#define CIN    2312
#define HID    300
#define NOUT   10
#define BATCH  128
#define T0     50
#define PAD    5
#define TP1    55          // T0 + PAD
#define T1     51          // conv1 output length
#define HP     56          // T1 + PAD
#define T2     52          // conv2 output length
#define KS     5
#define K1TOT  (KS*CIN)    // 11560
#define K2TOT  (KS*HID)    // 1500
#define M1     (BATCH*T1)  // 6528
#define M2     (BATCH*T2)  // 6656
#define BETA   0.9f
#define THRESH 1.0f

#define NIT    723                 // ceil(11560/16)
#define K1PAD  (NIT*16)            // 11568 (rows 11560..11567 of B1 stay zero)

// ---------------- scratch (device globals; zero-initialized, no allocation) ----------------
__device__ float g_Xpad[BATCH*TP1*CIN + 16];  // [B][55][CIN] + slack for padded-K over-read
__device__ float g_B1[(size_t)K1PAD*HID];     // [kk=(dt*CIN+i)][o]; pad rows never written => 0
__device__ float g_Y1[(size_t)M1*HID];        // [b*T1+t][HID]
__device__ float g_Hpad[BATCH*HP*HID];        // [B][56][HID]  spikes, left-padded
__device__ float g_B2t[NOUT*K2TOT];           // [o][kk=(dt*HID+h)]
__device__ float g_Y2[M2*NOUT];               // [b*T2+t][NOUT]

// ---------------- packed f32x2 helpers ----------------
__device__ __forceinline__ void fma2(unsigned long long& d,
                                     unsigned long long a,
                                     unsigned long long b) {
    asm("fma.rn.f32x2 %0, %1, %2, %3;" : "=l"(d) : "l"(a), "l"(b), "l"(d));
}
__device__ __forceinline__ void add2(unsigned long long& d, unsigned long long a) {
    asm("add.rn.f32x2 %0, %1, %2;" : "=l"(d) : "l"(d), "l"(a));
}

// ---------------- prep: pad + copy input ----------------
__global__ void prep_x(const float* __restrict__ data) {
    const int C4 = CIN / 4;                 // 578
    const int PER_B = TP1 * C4;             // 31790
    int v = blockIdx.x * blockDim.x + threadIdx.x;
    if (v >= BATCH * PER_B) return;
    int b = v / PER_B;
    int r = v - b * PER_B;
    int t = r / C4;
    int i4 = r - t * C4;
    float4 val = make_float4(0.f, 0.f, 0.f, 0.f);
    if (t >= PAD) {
        val = reinterpret_cast<const float4*>(data)[(b * T0 + (t - PAD)) * C4 + i4];
    }
    reinterpret_cast<float4*>(g_Xpad)[v] = val;
}

// ---------------- DCLS gaussian kernel synthesis ----------------
__device__ __forceinline__ void gauss5(float p, float g[KS]) {
    float c = p + 2.0f;
    float s = 0.f;
#pragma unroll
    for (int k = 0; k < KS; k++) {
        float d = ((float)k - c) * 0.5f;
        g[k] = expf(-0.5f * (d * d));
        s += g[k];
    }
    float den = s + 1e-7f;
#pragma unroll
    for (int k = 0; k < KS; k++) g[k] = g[k] / den;
}

__global__ void make_B1(const float* __restrict__ W1, const float* __restrict__ P1) {
    int tid = blockIdx.x * blockDim.x + threadIdx.x;
    if (tid >= CIN * HID) return;
    int i = tid / HID;
    int o = tid - i * HID;
    float w = W1[o * CIN + i];
    float p = P1[o * CIN + i];
    float g[KS];
    gauss5(p, g);
#pragma unroll
    for (int k = 0; k < KS; k++) {
        g_B1[(size_t)(k * CIN + i) * HID + o] = w * g[k];
    }
}

__global__ void make_B2(const float* __restrict__ W2, const float* __restrict__ P2) {
    int tid = blockIdx.x * blockDim.x + threadIdx.x;
    if (tid >= HID * NOUT) return;
    int h = tid / NOUT;
    int o = tid - h * NOUT;
    float w = W2[o * HID + h];
    float p = P2[o * HID + h];
    float g[KS];
    gauss5(p, g);
#pragma unroll
    for (int k = 0; k < KS; k++) {
        g_B2t[o * K2TOT + k * HID + h] = w * g[k];
    }
}

// ---------------- GEMM1, FFMA2 with conflict-free layouts ----------------
// Y1[m, o] = sum_kk A[m, kk] * B1[kk, o] + b1[o]
// BM=128, BN=64, BK=16, 256 threads. Micro-tile 8 M x 4 N per thread,
// accumulators paired along N: acc[i][j] = (y[m_i, n_2j], y[m_i, n_2j+1]).
//  - b pairs natural from Bs[kk][tc*4] (LDS.128, 16B stride: no replay)
//  - a (v,v) pairs from DUPLICATED Asd[kk][2m]; compute loads are 16-lane
//    broadcasts (conflict-free); dup stores are STS.64 stride 8B (conflict-free)
// Double-buffered, one __syncthreads per BK=16. Two-level accumulation:
// flush low->high every 16 iters (256 k terms) — same order as round 2.
__global__ void __launch_bounds__(256, 2) gemm1(const float* __restrict__ b1f) {
    __shared__ __align__(16) float Asd[2][16][256];   // duplicated A: [k][2m]=[k][2m+1]=A[m,k]
    __shared__ __align__(16) float Bs[2][16][64];     // natural B tile

    const int n0 = blockIdx.x * 64;
    const int m0 = blockIdx.y * 128;
    const int tid = threadIdx.x;

    // A loader: thread -> (row ar, k-offset ac4); 2 float4 per iter (BK=16)
    const int ar = tid >> 1;                  // 0..127
    const int ac4 = (tid & 1) * 4;            // 0 or 4
    const int m = m0 + ar;
    const int bb = m / T1;
    const int tt = m - bb * T1;
    const float* Arow = g_Xpad + (size_t)(bb * TP1 + tt) * CIN;

    // B loader: thread -> (k-row bkr, col bnc); 1 float4 per iter
    const int bkr = tid >> 4;                 // 0..15
    const int bnc = (tid & 15) * 4;           // 0..60
    const bool bload = (n0 + bnc + 3) < HID;
    const float* Bptr = g_B1 + (size_t)bkr * HID + n0 + bnc;
    const size_t bstep = (size_t)16 * HID;

    // compute mapping: rows tr*8..tr*8+7, cols tc*4..tc*4+3 (2 N-pairs)
    const int tr = tid >> 4;                  // 0..15
    const int tc = tid & 15;                  // 0..15

    typedef unsigned long long u64;
    u64 accL[8][2], accH[8][2];
#pragma unroll
    for (int i = 0; i < 8; i++)
#pragma unroll
        for (int j = 0; j < 2; j++) { accL[i][j] = 0ull; accH[i][j] = 0ull; }

    // helper lambda-ish macro: store duplicated A float4 into stage s rows k0r..k0r+3
#define STORE_A_DUP(s, k0r, v)                                                    \
    do {                                                                          \
        *reinterpret_cast<float2*>(&Asd[s][(k0r) + 0][2 * ar]) = make_float2((v).x, (v).x); \
        *reinterpret_cast<float2*>(&Asd[s][(k0r) + 1][2 * ar]) = make_float2((v).y, (v).y); \
        *reinterpret_cast<float2*>(&Asd[s][(k0r) + 2][2 * ar]) = make_float2((v).z, (v).z); \
        *reinterpret_cast<float2*>(&Asd[s][(k0r) + 3][2 * ar]) = make_float2((v).w, (v).w); \
    } while (0)

    // prologue: fill stage 0
    {
        float4 a0 = *reinterpret_cast<const float4*>(Arow + ac4);
        float4 a1 = *reinterpret_cast<const float4*>(Arow + 8 + ac4);
        float4 bv = make_float4(0.f, 0.f, 0.f, 0.f);
        if (bload) bv = *reinterpret_cast<const float4*>(Bptr);
        STORE_A_DUP(0, ac4, a0);
        STORE_A_DUP(0, 8 + ac4, a1);
        *reinterpret_cast<float4*>(&Bs[0][bkr][bnc]) = bv;
    }
    __syncthreads();

    for (int it = 0; it < NIT; ++it) {
        const int cur = it & 1;
        const bool more = (it + 1) < NIT;
        float4 a0n, a1n, bvn;
        if (more) {
            const float* Ap = Arow + (it + 1) * 16;
            a0n = *reinterpret_cast<const float4*>(Ap + ac4);
            a1n = *reinterpret_cast<const float4*>(Ap + 8 + ac4);
            bvn = make_float4(0.f, 0.f, 0.f, 0.f);
            if (bload) bvn = *reinterpret_cast<const float4*>(Bptr + (size_t)(it + 1) * bstep);
        }

#pragma unroll
        for (int kk = 0; kk < 16; kk++) {
            // 8 duplicated a-pairs (broadcast loads, conflict-free)
            ulonglong2 ap0 = *reinterpret_cast<const ulonglong2*>(&Asd[cur][kk][tr * 16 + 0]);
            ulonglong2 ap1 = *reinterpret_cast<const ulonglong2*>(&Asd[cur][kk][tr * 16 + 4]);
            ulonglong2 ap2 = *reinterpret_cast<const ulonglong2*>(&Asd[cur][kk][tr * 16 + 8]);
            ulonglong2 ap3 = *reinterpret_cast<const ulonglong2*>(&Asd[cur][kk][tr * 16 + 12]);
            // 2 natural b-pairs: (n0..n1),(n2..n3)
            ulonglong2 bq = *reinterpret_cast<const ulonglong2*>(&Bs[cur][kk][tc * 4]);

            fma2(accL[0][0], ap0.x, bq.x);  fma2(accL[0][1], ap0.x, bq.y);
            fma2(accL[1][0], ap0.y, bq.x);  fma2(accL[1][1], ap0.y, bq.y);
            fma2(accL[2][0], ap1.x, bq.x);  fma2(accL[2][1], ap1.x, bq.y);
            fma2(accL[3][0], ap1.y, bq.x);  fma2(accL[3][1], ap1.y, bq.y);
            fma2(accL[4][0], ap2.x, bq.x);  fma2(accL[4][1], ap2.x, bq.y);
            fma2(accL[5][0], ap2.y, bq.x);  fma2(accL[5][1], ap2.y, bq.y);
            fma2(accL[6][0], ap3.x, bq.x);  fma2(accL[6][1], ap3.x, bq.y);
            fma2(accL[7][0], ap3.y, bq.x);  fma2(accL[7][1], ap3.y, bq.y);
        }

        if ((it & 15) == 15) {     // flush every 256 k terms (same boundaries as round 2)
#pragma unroll
            for (int i = 0; i < 8; i++)
#pragma unroll
                for (int j = 0; j < 2; j++) { add2(accH[i][j], accL[i][j]); accL[i][j] = 0ull; }
        }

        if (more) {
            const int nxt = cur ^ 1;
            STORE_A_DUP(nxt, ac4, a0n);
            STORE_A_DUP(nxt, 8 + ac4, a1n);
            *reinterpret_cast<float4*>(&Bs[nxt][bkr][bnc]) = bvn;
            __syncthreads();
        }
    }
    // final flush (tail iters add exact zeros — numeric no-op)
#pragma unroll
    for (int i = 0; i < 8; i++)
#pragma unroll
        for (int j = 0; j < 2; j++) add2(accH[i][j], accL[i][j]);

    // epilogue: unpack N-pairs, add bias, store
#pragma unroll
    for (int i = 0; i < 8; i++) {
        int mm = m0 + tr * 8 + i;
        size_t row = (size_t)mm * HID;
#pragma unroll
        for (int j = 0; j < 2; j++) {
            float2 v = *reinterpret_cast<float2*>(&accH[i][j]);
            int n = n0 + tc * 4 + 2 * j;
            if (n < HID)     g_Y1[row + n]     = v.x + b1f[n];
            if (n + 1 < HID) g_Y1[row + n + 1] = v.y + b1f[n + 1];
        }
    }
#undef STORE_A_DUP
}

// ---------------- LIF layer 1 ----------------
__global__ void lif1() {
    int tid = blockIdx.x * blockDim.x + threadIdx.x;
    if (tid >= BATCH * HID) return;
    int b = tid / HID;
    int h = tid - b * HID;
#pragma unroll
    for (int tp = 0; tp < PAD; tp++)
        g_Hpad[(size_t)(b * HP + tp) * HID + h] = 0.f;
    float mem = 0.f;
    for (int t = 0; t < T1; t++) {
        float x = g_Y1[(size_t)(b * T1 + t) * HID + h];
        float reset = (mem > THRESH) ? 1.f : 0.f;
        mem = __fmaf_rn(BETA, mem, x) - reset * THRESH;
        float spk = (mem > THRESH) ? 1.f : 0.f;
        g_Hpad[(size_t)(b * HP + PAD + t) * HID + h] = spk;
    }
}

// ---------------- GEMM2: one warp per output row ----------------
__global__ void gemm2(const float* __restrict__ b2) {
    int gw = (blockIdx.x * blockDim.x + threadIdx.x) >> 5;
    int lane = threadIdx.x & 31;
    if (gw >= M2) return;
    int b = gw / T2;
    int t = gw - b * T2;
    const float* Arow = g_Hpad + (size_t)(b * HP + t) * HID;

    float acc[NOUT];
#pragma unroll
    for (int o = 0; o < NOUT; o++) acc[o] = 0.f;

    for (int kk = lane; kk < K2TOT; kk += 32) {
        float x = Arow[kk];
#pragma unroll
        for (int o = 0; o < NOUT; o++)
            acc[o] = __fmaf_rn(x, g_B2t[o * K2TOT + kk], acc[o]);
    }
#pragma unroll
    for (int o = 0; o < NOUT; o++) {
#pragma unroll
        for (int off = 16; off > 0; off >>= 1)
            acc[o] += __shfl_down_sync(0xffffffffu, acc[o], off);
    }
    if (lane == 0) {
#pragma unroll
        for (int o = 0; o < NOUT; o++)
            g_Y2[(size_t)gw * NOUT + o] = acc[o] + b2[o];
    }
}

// ---------------- LIF layer 2: spk2 and mem2 straight to d_out ----------------
__global__ void lif2(float* __restrict__ out) {
    int tid = blockIdx.x * blockDim.x + threadIdx.x;
    if (tid >= BATCH * NOUT) return;
    int b = tid / NOUT;
    int o = tid - b * NOUT;
    const int HALF = T2 * BATCH * NOUT;
    float mem = 0.f;
    for (int t = 0; t < T2; t++) {
        float x = g_Y2[(size_t)(b * T2 + t) * NOUT + o];
        float reset = (mem > THRESH) ? 1.f : 0.f;
        mem = __fmaf_rn(BETA, mem, x) - reset * THRESH;
        float spk = (mem > THRESH) ? 1.f : 0.f;
        int idx = (t * BATCH + b) * NOUT + o;
        out[idx] = spk;
        out[HALF + idx] = mem;
    }
}

// ---------------- launch ----------------
extern "C" void kernel_launch(void* const* d_in, const int* in_sizes, int n_in,
                              void* d_out, int out_size) {
    const float* data = (const float*)d_in[0];
    const float* W1   = (const float*)d_in[1];
    const float* P1   = (const float*)d_in[2];
    const float* b1   = (const float*)d_in[3];
    const float* W2   = (const float*)d_in[4];
    const float* P2   = (const float*)d_in[5];
    const float* b2   = (const float*)d_in[6];
    float* out = (float*)d_out;

    {
        int n4 = BATCH * TP1 * (CIN / 4);
        prep_x<<<(n4 + 255) / 256, 256>>>(data);
    }
    make_B1<<<(CIN * HID + 255) / 256, 256>>>(W1, P1);
    make_B2<<<(HID * NOUT + 255) / 256, 256>>>(W2, P2);

    {
        dim3 grid(5, 51);
        gemm1<<<grid, 256>>>(b1);
    }
    lif1<<<(BATCH * HID + 255) / 256, 256>>>();

    {
        int blocks = (M2 * 32 + 255) / 256;
        gemm2<<<blocks, 256>>>(b2);
    }
    lif2<<<(BATCH * NOUT + 255) / 256, 256>>>(out);
}

// round 5
// speedup vs baseline: 1.4323x; 1.0271x over previous
#include <cuda_runtime.h>

// ---------------- problem constants ----------------
#define CIN    2312
#define HID    300
#define NOUT   10
#define BATCH  128
#define T0     50
#define PAD    5
#define TP1    55          // T0 + PAD
#define T1     51          // conv1 output length
#define HP     56          // T1 + PAD
#define T2     52          // conv2 output length
#define KS     5
#define K1TOT  (KS*CIN)    // 11560
#define K2TOT  (KS*HID)    // 1500
#define M1     (BATCH*T1)  // 6528
#define M2     (BATCH*T2)  // 6656
#define BETA   0.9f
#define THRESH 1.0f

#define NIT    723                 // ceil(11560/16)
#define K1PAD  (NIT*16)            // 11568; kp rows 5780..5783 stay zero
#define KP_TOT (K1PAD/2)           // 5784 k-pairs

// ---------------- scratch (device globals; zero-initialized, no allocation) ----------------
__device__ float g_Xpad[BATCH*TP1*CIN + 16];   // [B][55][CIN] + slack for padded-K over-read
__device__ float g_B1p[(size_t)KP_TOT*2*HID];  // [kp][n][2]: (B[2kp,n],B[2kp+1,n]); pads = 0
__device__ float g_Y1[(size_t)M1*HID];         // [b*T1+t][HID]
__device__ float g_Hpad[BATCH*HP*HID];         // [B][56][HID]  spikes, left-padded
__device__ float g_B2t[NOUT*K2TOT];            // [o][kk=(dt*HID+h)]
__device__ float g_Y2[M2*NOUT];                // [b*T2+t][NOUT]

// ---------------- packed f32x2 helpers ----------------
__device__ __forceinline__ void fma2(unsigned long long& d,
                                     unsigned long long a,
                                     unsigned long long b) {
    asm("fma.rn.f32x2 %0, %1, %2, %0;" : "+l"(d) : "l"(a), "l"(b));
}

// ---------------- prep: pad + copy input ----------------
__global__ void prep_x(const float* __restrict__ data) {
    const int C4 = CIN / 4;                 // 578
    const int PER_B = TP1 * C4;             // 31790
    int v = blockIdx.x * blockDim.x + threadIdx.x;
    if (v >= BATCH * PER_B) return;
    int b = v / PER_B;
    int r = v - b * PER_B;
    int t = r / C4;
    int i4 = r - t * C4;
    float4 val = make_float4(0.f, 0.f, 0.f, 0.f);
    if (t >= PAD) {
        val = reinterpret_cast<const float4*>(data)[(b * T0 + (t - PAD)) * C4 + i4];
    }
    reinterpret_cast<float4*>(g_Xpad)[v] = val;
}

// ---------------- DCLS gaussian kernel synthesis ----------------
__device__ __forceinline__ void gauss5(float p, float g[KS]) {
    float c = p + 2.0f;
    float s = 0.f;
#pragma unroll
    for (int k = 0; k < KS; k++) {
        float d = ((float)k - c) * 0.5f;
        g[k] = expf(-0.5f * (d * d));
        s += g[k];
    }
    float den = s + 1e-7f;
#pragma unroll
    for (int k = 0; k < KS; k++) g[k] = g[k] / den;
}

// g_B1p[kp*2*HID + o*2 + e] = B1[2kp+e, o], where kk = dt*CIN + i
__global__ void make_B1(const float* __restrict__ W1, const float* __restrict__ P1) {
    int tid = blockIdx.x * blockDim.x + threadIdx.x;
    if (tid >= CIN * HID) return;
    int i = tid / HID;
    int o = tid - i * HID;
    float w = W1[o * CIN + i];
    float p = P1[o * CIN + i];
    float g[KS];
    gauss5(p, g);
#pragma unroll
    for (int k = 0; k < KS; k++) {
        int kk = k * CIN + i;
        g_B1p[(size_t)(kk >> 1) * (2 * HID) + o * 2 + (kk & 1)] = w * g[k];
    }
}

__global__ void make_B2(const float* __restrict__ W2, const float* __restrict__ P2) {
    int tid = blockIdx.x * blockDim.x + threadIdx.x;
    if (tid >= HID * NOUT) return;
    int h = tid / NOUT;
    int o = tid - h * NOUT;
    float w = W2[o * HID + h];
    float p = P2[o * HID + h];
    float g[KS];
    gauss5(p, g);
#pragma unroll
    for (int k = 0; k < KS; k++) {
        g_B2t[o * K2TOT + k * HID + h] = w * g[k];
    }
}

// ---------------- GEMM1, K-paired FFMA2 (no smem duplication) ----------------
// Y1[m, o] = sum_kk A[m, kk] * B1[kk, o] + b1[o]
// BM=64, BN=64, BK=16 (8 k-pairs), 256 threads, 4M x 4N micro-tile, k-paired accs.
// Asp[kp][m] float2 = (A[m,2kp],A[m,2kp+1]); Bsp[kp][n] float2 = (B[2kp,n],B[2kp+1,n]).
// Compute: per kp, 2 broadcast LDS.128 (a) + 2 contiguous LDS.128 (b) + 16 FFMA2.
// Row stride 66 float2 (pad 2) -> conflict-free stores. Two-level accumulation:
// flush accL (pairs) into scalar accH every 16 iters (128 k per lane).
#define F2STRIDE 66
__global__ void __launch_bounds__(256, 2) gemm1(const float* __restrict__ b1f) {
    __shared__ __align__(16) float2 Asp[2][8 * F2STRIDE];
    __shared__ __align__(16) float2 Bsp[2][8 * F2STRIDE];

    const int n0 = blockIdx.x * 64;
    const int m0 = blockIdx.y * 64;
    const int tid = threadIdx.x;

    // A loader: thread -> (row am, k-offset akq); one float4 (= 2 k-pairs) per iter
    const int am = tid >> 2;                  // 0..63
    const int akq = (tid & 3) * 4;            // 0,4,8,12
    const int akp = akq >> 1;                 // 0,2,4,6
    {
        // row pointer
    }
    const int m = m0 + am;
    const int bb = m / T1;
    const int tt = m - bb * T1;
    const float* Arow = g_Xpad + (size_t)(bb * TP1 + tt) * CIN + akq;

    // B loader: thread -> (kp-row bkp, n-offset bn2); one float4 (= pairs for n,n+1)
    const int bkp = tid >> 5;                 // 0..7
    const int bn2 = (tid & 31) * 2;           // 0..62
    const bool bvalid = (n0 + bn2 + 1) < HID; // pairs (n0+bn2, n0+bn2+1)
    const float* Bptr = g_B1p + (size_t)bkp * (2 * HID) + (size_t)(n0 + bn2) * 2;
    const size_t bstep = (size_t)8 * 2 * HID;

    // compute mapping: m_local = {2tr,2tr+1,2tr+32,2tr+33}, n_local = {2tc,2tc+1,2tc+32,2tc+33}
    const int tr = tid >> 4;                  // 0..15
    const int tc = tid & 15;                  // 0..15

    typedef unsigned long long u64;
    u64 accL[4][4];
    float accH[4][4];
#pragma unroll
    for (int i = 0; i < 4; i++)
#pragma unroll
        for (int j = 0; j < 4; j++) { accL[i][j] = 0ull; accH[i][j] = 0.f; }

    // prologue: fill stage 0
    {
        float4 av = *reinterpret_cast<const float4*>(Arow);
        float4 bv = make_float4(0.f, 0.f, 0.f, 0.f);
        if (bvalid) bv = *reinterpret_cast<const float4*>(Bptr);
        Asp[0][(akp + 0) * F2STRIDE + am] = make_float2(av.x, av.y);
        Asp[0][(akp + 1) * F2STRIDE + am] = make_float2(av.z, av.w);
        *reinterpret_cast<float4*>(&Bsp[0][bkp * F2STRIDE + bn2]) = bv;
    }
    __syncthreads();

    for (int it = 0; it < NIT; ++it) {
        const int cur = it & 1;
        const bool more = (it + 1) < NIT;
        float4 avn, bvn;
        if (more) {
            avn = *reinterpret_cast<const float4*>(Arow + (it + 1) * 16);
            bvn = make_float4(0.f, 0.f, 0.f, 0.f);
            if (bvalid) bvn = *reinterpret_cast<const float4*>(Bptr + (size_t)(it + 1) * bstep);
        }

#pragma unroll
        for (int kp = 0; kp < 8; kp++) {
            // a pairs for m_local 2tr,2tr+1 and 2tr+32,2tr+33 (broadcast loads)
            ulonglong2 ap01 = *reinterpret_cast<const ulonglong2*>(&Asp[cur][kp * F2STRIDE + 2 * tr]);
            ulonglong2 ap23 = *reinterpret_cast<const ulonglong2*>(&Asp[cur][kp * F2STRIDE + 2 * tr + 32]);
            // b pairs for n_local 2tc,2tc+1 and 2tc+32,2tc+33 (contiguous loads)
            ulonglong2 bp01 = *reinterpret_cast<const ulonglong2*>(&Bsp[cur][kp * F2STRIDE + 2 * tc]);
            ulonglong2 bp23 = *reinterpret_cast<const ulonglong2*>(&Bsp[cur][kp * F2STRIDE + 2 * tc + 32]);

            fma2(accL[0][0], ap01.x, bp01.x);  fma2(accL[0][1], ap01.x, bp01.y);
            fma2(accL[0][2], ap01.x, bp23.x);  fma2(accL[0][3], ap01.x, bp23.y);
            fma2(accL[1][0], ap01.y, bp01.x);  fma2(accL[1][1], ap01.y, bp01.y);
            fma2(accL[1][2], ap01.y, bp23.x);  fma2(accL[1][3], ap01.y, bp23.y);
            fma2(accL[2][0], ap23.x, bp01.x);  fma2(accL[2][1], ap23.x, bp01.y);
            fma2(accL[2][2], ap23.x, bp23.x);  fma2(accL[2][3], ap23.x, bp23.y);
            fma2(accL[3][0], ap23.y, bp01.x);  fma2(accL[3][1], ap23.y, bp01.y);
            fma2(accL[3][2], ap23.y, bp23.x);  fma2(accL[3][3], ap23.y, bp23.y);
        }

        if ((it & 15) == 15) {     // flush every 256 k terms (128 per lane)
#pragma unroll
            for (int i = 0; i < 4; i++)
#pragma unroll
                for (int j = 0; j < 4; j++) {
                    float2 v = *reinterpret_cast<float2*>(&accL[i][j]);
                    accH[i][j] += v.x;
                    accH[i][j] += v.y;
                    accL[i][j] = 0ull;
                }
        }

        if (more) {
            const int nxt = cur ^ 1;
            Asp[nxt][(akp + 0) * F2STRIDE + am] = make_float2(avn.x, avn.y);
            Asp[nxt][(akp + 1) * F2STRIDE + am] = make_float2(avn.z, avn.w);
            *reinterpret_cast<float4*>(&Bsp[nxt][bkp * F2STRIDE + bn2]) = bvn;
            __syncthreads();
        }
    }
    // final flush (tail iters contributed exact zeros)
#pragma unroll
    for (int i = 0; i < 4; i++)
#pragma unroll
        for (int j = 0; j < 4; j++) {
            float2 v = *reinterpret_cast<float2*>(&accL[i][j]);
            accH[i][j] += v.x;
            accH[i][j] += v.y;
        }

    // epilogue: add bias, store
    const int mloc[4] = {2 * tr, 2 * tr + 1, 2 * tr + 32, 2 * tr + 33};
    const int nloc[4] = {2 * tc, 2 * tc + 1, 2 * tc + 32, 2 * tc + 33};
#pragma unroll
    for (int i = 0; i < 4; i++) {
        size_t row = (size_t)(m0 + mloc[i]) * HID;
#pragma unroll
        for (int j = 0; j < 4; j++) {
            int n = n0 + nloc[j];
            if (n < HID) g_Y1[row + n] = accH[i][j] + b1f[n];
        }
    }
}

// ---------------- LIF layer 1 ----------------
__global__ void lif1() {
    int tid = blockIdx.x * blockDim.x + threadIdx.x;
    if (tid >= BATCH * HID) return;
    int b = tid / HID;
    int h = tid - b * HID;
#pragma unroll
    for (int tp = 0; tp < PAD; tp++)
        g_Hpad[(size_t)(b * HP + tp) * HID + h] = 0.f;
    float mem = 0.f;
    for (int t = 0; t < T1; t++) {
        float x = g_Y1[(size_t)(b * T1 + t) * HID + h];
        float reset = (mem > THRESH) ? 1.f : 0.f;
        mem = __fmaf_rn(BETA, mem, x) - reset * THRESH;
        float spk = (mem > THRESH) ? 1.f : 0.f;
        g_Hpad[(size_t)(b * HP + PAD + t) * HID + h] = spk;
    }
}

// ---------------- GEMM2: one warp per output row ----------------
__global__ void gemm2(const float* __restrict__ b2) {
    int gw = (blockIdx.x * blockDim.x + threadIdx.x) >> 5;
    int lane = threadIdx.x & 31;
    if (gw >= M2) return;
    int b = gw / T2;
    int t = gw - b * T2;
    const float* Arow = g_Hpad + (size_t)(b * HP + t) * HID;

    float acc[NOUT];
#pragma unroll
    for (int o = 0; o < NOUT; o++) acc[o] = 0.f;

    for (int kk = lane; kk < K2TOT; kk += 32) {
        float x = Arow[kk];
#pragma unroll
        for (int o = 0; o < NOUT; o++)
            acc[o] = __fmaf_rn(x, g_B2t[o * K2TOT + kk], acc[o]);
    }
#pragma unroll
    for (int o = 0; o < NOUT; o++) {
#pragma unroll
        for (int off = 16; off > 0; off >>= 1)
            acc[o] += __shfl_down_sync(0xffffffffu, acc[o], off);
    }
    if (lane == 0) {
#pragma unroll
        for (int o = 0; o < NOUT; o++)
            g_Y2[(size_t)gw * NOUT + o] = acc[o] + b2[o];
    }
}

// ---------------- LIF layer 2: spk2 and mem2 straight to d_out ----------------
__global__ void lif2(float* __restrict__ out) {
    int tid = blockIdx.x * blockDim.x + threadIdx.x;
    if (tid >= BATCH * NOUT) return;
    int b = tid / NOUT;
    int o = tid - b * NOUT;
    const int HALF = T2 * BATCH * NOUT;
    float mem = 0.f;
    for (int t = 0; t < T2; t++) {
        float x = g_Y2[(size_t)(b * T2 + t) * NOUT + o];
        float reset = (mem > THRESH) ? 1.f : 0.f;
        mem = __fmaf_rn(BETA, mem, x) - reset * THRESH;
        float spk = (mem > THRESH) ? 1.f : 0.f;
        int idx = (t * BATCH + b) * NOUT + o;
        out[idx] = spk;
        out[HALF + idx] = mem;
    }
}

// ---------------- launch ----------------
extern "C" void kernel_launch(void* const* d_in, const int* in_sizes, int n_in,
                              void* d_out, int out_size) {
    const float* data = (const float*)d_in[0];
    const float* W1   = (const float*)d_in[1];
    const float* P1   = (const float*)d_in[2];
    const float* b1   = (const float*)d_in[3];
    const float* W2   = (const float*)d_in[4];
    const float* P2   = (const float*)d_in[5];
    const float* b2   = (const float*)d_in[6];
    float* out = (float*)d_out;

    {
        int n4 = BATCH * TP1 * (CIN / 4);
        prep_x<<<(n4 + 255) / 256, 256>>>(data);
    }
    make_B1<<<(CIN * HID + 255) / 256, 256>>>(W1, P1);
    make_B2<<<(HID * NOUT + 255) / 256, 256>>>(W2, P2);

    {
        dim3 grid(5, 102);     // 64-col x 64-row tiles: 5*64>=300, 102*64=6528
        gemm1<<<grid, 256>>>(b1);
    }
    lif1<<<(BATCH * HID + 255) / 256, 256>>>();

    {
        int blocks = (M2 * 32 + 255) / 256;
        gemm2<<<blocks, 256>>>(b2);
    }
    lif2<<<(BATCH * NOUT + 255) / 256, 256>>>(out);
}

// round 14
// speedup vs baseline: 1.7269x; 1.2056x over previous
#include <cuda_runtime.h>
#include <cstdint>

// ---------------- problem constants ----------------
#define CIN    2312
#define HID    300
#define NOUT   10
#define BATCH  128
#define T0     50
#define PAD    5
#define TP1    55          // T0 + PAD
#define T1     51          // conv1 output length
#define HP     56          // T1 + PAD
#define T2     52          // conv2 output length
#define KS     5
#define K1TOT  (KS*CIN)    // 11560
#define K2TOT  (KS*HID)    // 1500
#define M1     (BATCH*T1)  // 6528
#define M2     (BATCH*T2)  // 6656
#define BETA   0.9f
#define THRESH 1.0f

// GEMM1 (mma.sync tf32, split-K) config
#define NPART  8                    // split-K parts
#define NSTG   91                   // stages of BK=16 per part
#define KPART  (NSTG*16)            // 1456 K per part
#define K1PADB (NPART*KPART)        // 11648 (cols 11560.. stay zero)
#define NPADB  320                  // N padded to 5 CTA tiles of 64
#define FLUSH  4                    // acc->accH flush period (stages)

// smem tile geometry (floats)
#define ASTRIDE 20                  // 16 k + pad 4 -> 80B rows (odd x 16B: LDSM conflict-free)
#define ATILE_F (128*ASTRIDE)       // 2560
#define BTILE_F (64*ASTRIDE)        // 1280
#define STAGE_F (2*ATILE_F + 2*BTILE_F)   // 7680 floats = 30720 B
#define SMEM_DYN (2*STAGE_F*4)      // 61440 B

// ---------------- scratch (device globals; zero-initialized, no allocation) ----------------
// +128 slack: last im2col row + padded-K over-read (max k offset 11648, row start
// 16,264,920, array data end 16,276,480) stays in-bounds; slack is zero-init.
__device__ __align__(16) float g_Xh[BATCH*TP1*CIN + 128];     // tf32-hi of padded input
__device__ __align__(16) float g_Xl[BATCH*TP1*CIN + 128];     // tf32(lo) residual
__device__ __align__(16) float g_B1h[(size_t)NPADB*K1PADB];   // [n][k] K-major, hi
__device__ __align__(16) float g_B1l[(size_t)NPADB*K1PADB];   // [n][k] K-major, lo
__device__ float g_Y1p[(size_t)NPART*M1*NPADB];                // split-K partials
__device__ float g_Y1[(size_t)M1*HID];                         // [b*T1+t][HID]
__device__ float g_Hpad[BATCH*HP*HID];                         // [B][56][HID] spikes, padded
__device__ float g_B2t[NOUT*K2TOT];                            // [o][kk=(dt*HID+h)]
__device__ float g_Y2[M2*NOUT];                                // [b*T2+t][NOUT]

// ---------------- PTX helpers (compute_80-era only; compile for compute_103) ----------------
__device__ __forceinline__ uint32_t smem_u32(const void* p) {
    uint32_t a;
    asm("{ .reg .u64 t; cvta.to.shared.u64 t, %1; cvt.u32.u64 %0, t; }" : "=r"(a) : "l"(p));
    return a;
}
__device__ __forceinline__ float tf32_rna(float v) {
    float h;
    asm("cvt.rna.tf32.f32 %0, %1;" : "=f"(h) : "f"(v));
    return h;
}
__device__ __forceinline__ void ldsm4(uint32_t* r, uint32_t addr) {
    asm volatile("ldmatrix.sync.aligned.m8n8.x4.shared.b16 {%0,%1,%2,%3}, [%4];"
        : "=r"(r[0]), "=r"(r[1]), "=r"(r[2]), "=r"(r[3]) : "r"(addr));
}
__device__ __forceinline__ void mma_tf32(float* d, const uint32_t* a, uint32_t b0, uint32_t b1) {
    asm volatile(
        "mma.sync.aligned.m16n8k8.row.col.f32.tf32.tf32.f32 "
        "{%0,%1,%2,%3}, {%4,%5,%6,%7}, {%8,%9}, {%0,%1,%2,%3};"
        : "+f"(d[0]), "+f"(d[1]), "+f"(d[2]), "+f"(d[3])
        : "r"(a[0]), "r"(a[1]), "r"(a[2]), "r"(a[3]), "r"(b0), "r"(b1));
}

// ---------------- prep: pad + copy input, tf32-split ----------------
__global__ void prep_x(const float* __restrict__ data) {
    const int C4 = CIN / 4;                 // 578
    const int PER_B = TP1 * C4;             // 31790
    int v = blockIdx.x * blockDim.x + threadIdx.x;
    if (v >= BATCH * PER_B) return;
    int b = v / PER_B;
    int r = v - b * PER_B;
    int t = r / C4;
    int i4 = r - t * C4;
    float4 val = make_float4(0.f, 0.f, 0.f, 0.f);
    if (t >= PAD) {
        val = reinterpret_cast<const float4*>(data)[(b * T0 + (t - PAD)) * C4 + i4];
    }
    float4 h = make_float4(tf32_rna(val.x), tf32_rna(val.y), tf32_rna(val.z), tf32_rna(val.w));
    float4 l = make_float4(tf32_rna(val.x - h.x), tf32_rna(val.y - h.y),
                           tf32_rna(val.z - h.z), tf32_rna(val.w - h.w));
    reinterpret_cast<float4*>(g_Xh)[v] = h;
    reinterpret_cast<float4*>(g_Xl)[v] = l;
}

// ---------------- DCLS gaussian kernel synthesis ----------------
__device__ __forceinline__ void gauss5(float p, float g[KS]) {
    float c = p + 2.0f;
    float s = 0.f;
#pragma unroll
    for (int k = 0; k < KS; k++) {
        float d = ((float)k - c) * 0.5f;
        g[k] = expf(-0.5f * (d * d));
        s += g[k];
    }
    float den = s + 1e-7f;
#pragma unroll
    for (int k = 0; k < KS; k++) g[k] = g[k] / den;
}

// B1h/B1l[n][kk], kk = dt*CIN + i (tf32 split)
__global__ void make_B1(const float* __restrict__ W1, const float* __restrict__ P1) {
    int tid = blockIdx.x * blockDim.x + threadIdx.x;
    if (tid >= CIN * HID) return;
    int o = tid / CIN;
    int i = tid - o * CIN;
    float w = W1[o * CIN + i];
    float p = P1[o * CIN + i];
    float g[KS];
    gauss5(p, g);
#pragma unroll
    for (int k = 0; k < KS; k++) {
        float v = w * g[k];
        float h = tf32_rna(v);
        size_t idx = (size_t)o * K1PADB + k * CIN + i;
        g_B1h[idx] = h;
        g_B1l[idx] = tf32_rna(v - h);
    }
}

__global__ void make_B2(const float* __restrict__ W2, const float* __restrict__ P2) {
    int tid = blockIdx.x * blockDim.x + threadIdx.x;
    if (tid >= HID * NOUT) return;
    int h = tid / NOUT;
    int o = tid - h * NOUT;
    float w = W2[o * HID + h];
    float p = P2[o * HID + h];
    float g[KS];
    gauss5(p, g);
#pragma unroll
    for (int k = 0; k < KS; k++) {
        g_B2t[o * K2TOT + k * HID + h] = w * g[k];
    }
}

// ---------------- GEMM1 via mma.sync m16n8k8 tf32, 3xTF32 split, split-K=8 ----------------
// CTA 128x64, BK=16, 256 threads = 8 warps (4m x 2n), warp tile 32x32.
// Per k8 per warp: 8 LDSM.x4 + 24 MMA (hi*hi + hi*lo + lo*hi).
// blockIdx.z selects K part; acc flushed into accH every 4 stages.
__global__ void __launch_bounds__(256, 2) gemm1_mma() {
    extern __shared__ float sm[];
    const uint32_t smb = smem_u32(sm);
    const int tid = threadIdx.x;
    const int wid = tid >> 5;
    const int l = tid & 31;
    const int n0 = blockIdx.x * 64;
    const int m0 = blockIdx.y * 128;
    const int part = blockIdx.z;
    const int kbase = part * KPART;
    const int warp_m = wid & 3;
    const int warp_n = wid >> 2;

    // ---- loader mappings ----
    const int ar = tid >> 1;
    const int ah = tid & 1;
    const int m = m0 + ar;
    const int bb = m / T1;
    const int tt = m - bb * T1;
    const float* pAh = g_Xh + (size_t)(bb * TP1 + tt) * CIN + kbase + ah * 8;
    const float* pAl = g_Xl + (size_t)(bb * TP1 + tt) * CIN + kbase + ah * 8;
    const int br = (tid & 127) >> 1;
    const int bh2 = tid & 1;
    const bool isBlo = tid >= 128;
    const float* pB = (isBlo ? g_B1l : g_B1h) + (size_t)(n0 + br) * K1PADB + kbase + bh2 * 8;

    float* sA = sm + ar * ASTRIDE + ah * 8;
    float* sB = sm + 2 * ATILE_F + (isBlo ? BTILE_F : 0) + br * ASTRIDE + bh2 * 8;

    // ---- LDSM address offsets ----
    const int lds_row = ((l >> 3) & 1) * 8 + (l & 7);
    const int lds_k = (l >> 4) * 4;
    const int aoff = (warp_m * 32 + lds_row) * ASTRIDE + lds_k;
    const int boff = (warp_n * 32 + lds_row) * ASTRIDE + lds_k;
    uint32_t aAddr[2], bAddr[2];
#pragma unroll
    for (int st = 0; st < 2; st++) {
        aAddr[st] = smb + (uint32_t)(st * STAGE_F + aoff) * 4u;
        bAddr[st] = smb + (uint32_t)(st * STAGE_F + 2 * ATILE_F + boff) * 4u;
    }

    float acc[2][4][4], accH[2][4][4];
#pragma unroll
    for (int i = 0; i < 2; i++)
#pragma unroll
        for (int j = 0; j < 4; j++)
#pragma unroll
            for (int q = 0; q < 4; q++) { acc[i][j][q] = 0.f; accH[i][j][q] = 0.f; }

    // ---- prologue: fill stage 0 ----
    {
        float4 vh0 = *reinterpret_cast<const float4*>(pAh);
        float4 vh1 = *reinterpret_cast<const float4*>(pAh + 4);
        float4 vl0 = *reinterpret_cast<const float4*>(pAl);
        float4 vl1 = *reinterpret_cast<const float4*>(pAl + 4);
        float4 w0 = *reinterpret_cast<const float4*>(pB);
        float4 w1 = *reinterpret_cast<const float4*>(pB + 4);
        *reinterpret_cast<float4*>(sA) = vh0;
        *reinterpret_cast<float4*>(sA + 4) = vh1;
        *reinterpret_cast<float4*>(sA + ATILE_F) = vl0;
        *reinterpret_cast<float4*>(sA + ATILE_F + 4) = vl1;
        *reinterpret_cast<float4*>(sB) = w0;
        *reinterpret_cast<float4*>(sB + 4) = w1;
    }
    __syncthreads();

    int fc = 0;
    for (int s = 0; s < NSTG; ++s) {
        const int cur = s & 1;
        const bool more = (s + 1) < NSTG;
        float4 vh0, vh1, vl0, vl1, w0, w1;
        if (more) {
            const int ko = (s + 1) * 16;
            vh0 = *reinterpret_cast<const float4*>(pAh + ko);
            vh1 = *reinterpret_cast<const float4*>(pAh + ko + 4);
            vl0 = *reinterpret_cast<const float4*>(pAl + ko);
            vl1 = *reinterpret_cast<const float4*>(pAl + ko + 4);
            w0 = *reinterpret_cast<const float4*>(pB + ko);
            w1 = *reinterpret_cast<const float4*>(pB + ko + 4);
        }

        // ---- compute stage s: 2 k8 steps ----
#pragma unroll
        for (int kb = 0; kb < 2; kb++) {
            const uint32_t kbyte = (uint32_t)(kb * 8 * 4);
            uint32_t ahf[2][4], alf[2][4], bhf[2][4], blf[2][4];
#pragma unroll
            for (int mt = 0; mt < 2; mt++) {
                uint32_t base = aAddr[cur] + (uint32_t)(mt * 16 * ASTRIDE * 4) + kbyte;
                ldsm4(ahf[mt], base);
                ldsm4(alf[mt], base + (uint32_t)(ATILE_F * 4));
            }
#pragma unroll
            for (int t16 = 0; t16 < 2; t16++) {
                uint32_t base = bAddr[cur] + (uint32_t)(t16 * 16 * ASTRIDE * 4) + kbyte;
                ldsm4(bhf[t16], base);
                ldsm4(blf[t16], base + (uint32_t)(BTILE_F * 4));
            }
#pragma unroll
            for (int mt = 0; mt < 2; mt++) {
#pragma unroll
                for (int nt = 0; nt < 4; nt++) {
                    const int g = nt >> 1, w8 = nt & 1;
                    mma_tf32(acc[mt][nt], ahf[mt], bhf[g][w8], bhf[g][w8 + 2]);
                    mma_tf32(acc[mt][nt], ahf[mt], blf[g][w8], blf[g][w8 + 2]);
                    mma_tf32(acc[mt][nt], alf[mt], bhf[g][w8], bhf[g][w8 + 2]);
                }
            }
        }

        // ---- frequent flush: bound fp32 accumulation chain ----
        if (++fc == FLUSH || !more) {
            fc = 0;
#pragma unroll
            for (int i = 0; i < 2; i++)
#pragma unroll
                for (int j = 0; j < 4; j++)
#pragma unroll
                    for (int q = 0; q < 4; q++) { accH[i][j][q] += acc[i][j][q]; acc[i][j][q] = 0.f; }
        }

        // ---- store next stage, sync ----
        if (more) {
            const int nf = (cur ^ 1) * STAGE_F;
            *reinterpret_cast<float4*>(sA + nf) = vh0;
            *reinterpret_cast<float4*>(sA + nf + 4) = vh1;
            *reinterpret_cast<float4*>(sA + nf + ATILE_F) = vl0;
            *reinterpret_cast<float4*>(sA + nf + ATILE_F + 4) = vl1;
            *reinterpret_cast<float4*>(sB + nf) = w0;
            *reinterpret_cast<float4*>(sB + nf + 4) = w1;
            __syncthreads();
        }
    }

    // ---- epilogue: write partials (full NPADB stride, no bias) ----
    float* outp = g_Y1p + (size_t)part * M1 * NPADB;
#pragma unroll
    for (int mt = 0; mt < 2; mt++) {
        const int r0 = m0 + warp_m * 32 + mt * 16 + (l >> 2);
#pragma unroll
        for (int nt = 0; nt < 4; nt++) {
            const int c = n0 + warp_n * 32 + nt * 8 + (l & 3) * 2;
            const float* d = accH[mt][nt];
            *reinterpret_cast<float2*>(outp + (size_t)r0 * NPADB + c) = make_float2(d[0], d[1]);
            *reinterpret_cast<float2*>(outp + (size_t)(r0 + 8) * NPADB + c) = make_float2(d[2], d[3]);
        }
    }
}

// ---------------- reduce split-K partials (8-way pairwise) + bias -> g_Y1 ----------------
__global__ void reduce1(const float* __restrict__ b1f) {
    int idx = blockIdx.x * blockDim.x + threadIdx.x;
    if (idx >= M1 * HID) return;
    int mrow = idx / HID;
    int n = idx - mrow * HID;
    size_t off = (size_t)mrow * NPADB + n;
    const size_t PSZ = (size_t)M1 * NPADB;
    float p0 = g_Y1p[off];
    float p1 = g_Y1p[off + PSZ];
    float p2 = g_Y1p[off + 2 * PSZ];
    float p3 = g_Y1p[off + 3 * PSZ];
    float p4 = g_Y1p[off + 4 * PSZ];
    float p5 = g_Y1p[off + 5 * PSZ];
    float p6 = g_Y1p[off + 6 * PSZ];
    float p7 = g_Y1p[off + 7 * PSZ];
    float s = ((p0 + p1) + (p2 + p3)) + ((p4 + p5) + (p6 + p7));
    g_Y1[idx] = s + b1f[n];
}

// ---------------- LIF layer 1 ----------------
__global__ void lif1() {
    int tid = blockIdx.x * blockDim.x + threadIdx.x;
    if (tid >= BATCH * HID) return;
    int b = tid / HID;
    int h = tid - b * HID;
#pragma unroll
    for (int tp = 0; tp < PAD; tp++)
        g_Hpad[(size_t)(b * HP + tp) * HID + h] = 0.f;
    float mem = 0.f;
    for (int t = 0; t < T1; t++) {
        float x = g_Y1[(size_t)(b * T1 + t) * HID + h];
        float reset = (mem > THRESH) ? 1.f : 0.f;
        mem = __fmaf_rn(BETA, mem, x) - reset * THRESH;
        float spk = (mem > THRESH) ? 1.f : 0.f;
        g_Hpad[(size_t)(b * HP + PAD + t) * HID + h] = spk;
    }
}

// ---------------- GEMM2: one warp per output row ----------------
__global__ void gemm2(const float* __restrict__ b2) {
    int gw = (blockIdx.x * blockDim.x + threadIdx.x) >> 5;
    int lane = threadIdx.x & 31;
    if (gw >= M2) return;
    int b = gw / T2;
    int t = gw - b * T2;
    const float* Arow = g_Hpad + (size_t)(b * HP + t) * HID;

    float acc[NOUT];
#pragma unroll
    for (int o = 0; o < NOUT; o++) acc[o] = 0.f;

    for (int kk = lane; kk < K2TOT; kk += 32) {
        float x = Arow[kk];
#pragma unroll
        for (int o = 0; o < NOUT; o++)
            acc[o] = __fmaf_rn(x, g_B2t[o * K2TOT + kk], acc[o]);
    }
#pragma unroll
    for (int o = 0; o < NOUT; o++) {
#pragma unroll
        for (int off = 16; off > 0; off >>= 1)
            acc[o] += __shfl_down_sync(0xffffffffu, acc[o], off);
    }
    if (lane == 0) {
#pragma unroll
        for (int o = 0; o < NOUT; o++)
            g_Y2[(size_t)gw * NOUT + o] = acc[o] + b2[o];
    }
}

// ---------------- LIF layer 2: spk2 and mem2 straight to d_out ----------------
__global__ void lif2(float* __restrict__ out) {
    int tid = blockIdx.x * blockDim.x + threadIdx.x;
    if (tid >= BATCH * NOUT) return;
    int b = tid / NOUT;
    int o = tid - b * NOUT;
    const int HALF = T2 * BATCH * NOUT;
    float mem = 0.f;
    for (int t = 0; t < T2; t++) {
        float x = g_Y2[(size_t)(b * T2 + t) * NOUT + o];
        float reset = (mem > THRESH) ? 1.f : 0.f;
        mem = __fmaf_rn(BETA, mem, x) - reset * THRESH;
        float spk = (mem > THRESH) ? 1.f : 0.f;
        int idx = (t * BATCH + b) * NOUT + o;
        out[idx] = spk;
        out[HALF + idx] = mem;
    }
}

// ---------------- launch ----------------
extern "C" void kernel_launch(void* const* d_in, const int* in_sizes, int n_in,
                              void* d_out, int out_size) {
    const float* data = (const float*)d_in[0];
    const float* W1   = (const float*)d_in[1];
    const float* P1   = (const float*)d_in[2];
    const float* b1   = (const float*)d_in[3];
    const float* W2   = (const float*)d_in[4];
    const float* P2   = (const float*)d_in[5];
    const float* b2   = (const float*)d_in[6];
    float* out = (float*)d_out;

    (void)cudaFuncSetAttribute(gemm1_mma, cudaFuncAttributeMaxDynamicSharedMemorySize, SMEM_DYN);

    {
        int n4 = BATCH * TP1 * (CIN / 4);
        prep_x<<<(n4 + 255) / 256, 256>>>(data);
    }
    make_B1<<<(CIN * HID + 255) / 256, 256>>>(W1, P1);
    make_B2<<<(HID * NOUT + 255) / 256, 256>>>(W2, P2);

    {
        dim3 grid(5, 51, NPART);   // 5 N-tiles x 51 M-tiles x 8 K-parts = 2040 CTAs
        gemm1_mma<<<grid, 256, SMEM_DYN>>>();
    }
    reduce1<<<(M1 * HID + 255) / 256, 256>>>(b1);
    lif1<<<(BATCH * HID + 255) / 256, 256>>>();

    {
        int blocks = (M2 * 32 + 255) / 256;
        gemm2<<<blocks, 256>>>(b2);
    }
    lif2<<<(BATCH * NOUT + 255) / 256, 256>>>(out);
}